// round 12
// baseline (speedup 1.0000x reference)
#include <cuda_runtime.h>
#include <cuda_bf16.h>
#include <math.h>

// Problem constants
#define BB 32
#define SS 1024
#define EE 512
#define HH 256
#define G4 1024          // 4*H

// ---------------- static scratch (no allocations) ----------------
__device__ float    g_xg[(size_t)2 * SS * G4 * BB];     // [d][t][g][b]
__device__ float    g_WT[(size_t)2 * EE * G4];          // [d][e][g]
__device__ int      g_tok[2 * SS * BB];                 // [d][t*32+b]
__device__ int      g_j[2 * SS * BB];                   // [d][t*32+b] out row or -1
__device__ float    g_hprev[2][2][HH * BB];             // [d][buf][k*32+b]
__device__ unsigned g_cnt[2];

__device__ __forceinline__ float sigm(float x) { return 1.0f / (1.0f + __expf(-x)); }

__device__ __forceinline__ void fma2(unsigned long long &d,
                                     unsigned long long a, unsigned long long b) {
    asm("fma.rn.f32x2 %0, %1, %2, %0;" : "+l"(d) : "l"(a), "l"(b));
}
__device__ __forceinline__ unsigned long long add2(unsigned long long a,
                                                   unsigned long long b) {
    unsigned long long r;
    asm("add.rn.f32x2 %0, %1, %2;" : "=l"(r) : "l"(a), "l"(b));
    return r;
}
__device__ __forceinline__ unsigned long long dup2(float x) {
    unsigned long long r; asm("mov.b64 %0, {%1, %1};" : "=l"(r) : "f"(x)); return r;
}
__device__ __forceinline__ float2 unpk(unsigned long long v) {
    float2 r; asm("mov.b64 {%0, %1}, %2;" : "=f"(r.x), "=f"(r.y) : "l"(v)); return r;
}

// ---------------- prep: inverse permutation, token arrays, state reset --------
__global__ __launch_bounds__(1024) void k_prep(const int* __restrict__ inputs,
                                               const int* __restrict__ seqlen,
                                               const int* __restrict__ fmask)
{
    int b = blockIdx.x;
    int t = threadIdx.x;
    __shared__ int sc[SS];
    int m = (fmask[b * SS + t] != 0) ? 1 : 0;
    sc[t] = m;
    __syncthreads();
    for (int off = 1; off < SS; off <<= 1) {
        int v = (t >= off) ? sc[t - off] : 0;
        __syncthreads();
        sc[t] += v;
        __syncthreads();
    }
    int r   = sc[t];          // inclusive rank
    int cnt = sc[SS - 1];
    g_j[t * BB + b]           = m ? (r - 1)   : -1;   // fwd out row
    g_j[SS * BB + t * BB + b] = m ? (cnt - r) : -1;   // bwd out row

    int len = seqlen[b];
    g_tok[t * BB + b] = inputs[b * SS + t];
    g_tok[SS * BB + t * BB + b] = (t < len) ? inputs[b * SS + (len - 1 - t)] : 0;

    if (b == 0) {
        for (int i = t; i < 2 * HH * BB; i += 1024) {
            int d = i / (HH * BB);
            g_hprev[d][0][i - d * HH * BB] = 0.0f;
        }
        if (t < 2) g_cnt[t] = 0u;
    }
}

// ---------------- tiled transpose W_ih[g][e] -> WT[e][g] -----------------------
__global__ __launch_bounds__(256) void k_wt(const float* __restrict__ fW,
                                            const float* __restrict__ bW)
{
    __shared__ float tile[32][33];
    int d  = blockIdx.z;
    int g0 = blockIdx.x * 32;
    int e0 = blockIdx.y * 32;
    const float* W = d ? bW : fW;
    int tx = threadIdx.x & 31, ty = threadIdx.x >> 5;  // 32 x 8
#pragma unroll
    for (int j = 0; j < 4; j++) {
        int g = g0 + ty + j * 8;
        tile[ty + j * 8][tx] = W[(size_t)g * EE + e0 + tx];
    }
    __syncthreads();
#pragma unroll
    for (int j = 0; j < 4; j++) {
        int e = e0 + ty + j * 8;
        g_WT[(size_t)d * EE * G4 + (size_t)e * G4 + g0 + tx] = tile[tx][ty + j * 8];
    }
}

// ---------------- xg GEMM: 128x128 tile, 8x8 micro, f32x2 (R7 version) ---------
__global__ __launch_bounds__(256) void k_gemm(
    const float* __restrict__ emb,
    const float* __restrict__ fbih, const float* __restrict__ fbhh,
    const float* __restrict__ bbih, const float* __restrict__ bbhh)
{
    const int d  = blockIdx.z;
    const int g0 = blockIdx.y * 128;
    const int n0 = blockIdx.x * 128;
    const float* __restrict__ WT  = g_WT + (size_t)d * EE * G4;
    const int*   __restrict__ tok = g_tok + d * SS * BB;
    const float* __restrict__ bih = d ? bbih : fbih;
    const float* __restrict__ bhh = d ? bbhh : fbhh;

    __shared__ __align__(16) float As[16 * 128];      // [k][m]
    __shared__ __align__(16) float Bs[16 * 132];      // [k][n] padded
    __shared__ int ts[128];

    const int tid = threadIdx.x;
    if (tid < 128) ts[tid] = tok[n0 + tid];
    __syncthreads();

    const int ty = tid >> 4;      // m octet
    const int tx = tid & 15;      // n octet

    const int akr = tid >> 5;            // k row (and +8)
    const int am4 = (tid & 31) * 4;
    const int bn  = tid >> 2;            // n (and +64)
    const int bk4 = (tid & 3) * 4;
    const size_t arow0 = (size_t)akr * G4 + g0 + am4;
    const size_t arow1 = (size_t)(akr + 8) * G4 + g0 + am4;
    const size_t brow0 = (size_t)ts[bn] * EE + bk4;
    const size_t brow1 = (size_t)ts[bn + 64] * EE + bk4;

    unsigned long long acc[8][4] = {};

    float4 pa0 = *(const float4*)(WT + arow0);
    float4 pa1 = *(const float4*)(WT + arow1);
    float4 pb0 = *(const float4*)(emb + brow0);
    float4 pb1 = *(const float4*)(emb + brow1);

    for (int kt = 0; kt < 32; kt++) {
        *(float4*)&As[akr * 128 + am4]       = pa0;
        *(float4*)&As[(akr + 8) * 128 + am4] = pa1;
        Bs[(bk4 + 0) * 132 + bn] = pb0.x;  Bs[(bk4 + 1) * 132 + bn] = pb0.y;
        Bs[(bk4 + 2) * 132 + bn] = pb0.z;  Bs[(bk4 + 3) * 132 + bn] = pb0.w;
        Bs[(bk4 + 0) * 132 + bn + 64] = pb1.x;  Bs[(bk4 + 1) * 132 + bn + 64] = pb1.y;
        Bs[(bk4 + 2) * 132 + bn + 64] = pb1.z;  Bs[(bk4 + 3) * 132 + bn + 64] = pb1.w;
        __syncthreads();

        if (kt < 31) {
            int k0 = (kt + 1) * 16;
            pa0 = *(const float4*)(WT + (size_t)k0 * G4 + arow0);
            pa1 = *(const float4*)(WT + (size_t)k0 * G4 + arow1);
            pb0 = *(const float4*)(emb + brow0 + k0);
            pb1 = *(const float4*)(emb + brow1 + k0);
        }

#pragma unroll
        for (int k = 0; k < 16; k++) {
            float4 af0 = *(float4*)&As[k * 128 + ty * 8];
            float4 af1 = *(float4*)&As[k * 128 + ty * 8 + 4];
            ulonglong2 bq0 = *(ulonglong2*)&Bs[k * 132 + tx * 8];
            ulonglong2 bq1 = *(ulonglong2*)&Bs[k * 132 + tx * 8 + 4];
            unsigned long long ad[8];
            ad[0] = dup2(af0.x); ad[1] = dup2(af0.y);
            ad[2] = dup2(af0.z); ad[3] = dup2(af0.w);
            ad[4] = dup2(af1.x); ad[5] = dup2(af1.y);
            ad[6] = dup2(af1.z); ad[7] = dup2(af1.w);
#pragma unroll
            for (int i = 0; i < 8; i++) {
                fma2(acc[i][0], ad[i], bq0.x);
                fma2(acc[i][1], ad[i], bq0.y);
                fma2(acc[i][2], ad[i], bq1.x);
                fma2(acc[i][3], ad[i], bq1.y);
            }
        }
        __syncthreads();
    }

    int nb = n0 + tx * 8;
    int t  = nb >> 5;
    int b0 = nb & 31;
    size_t base_d = (size_t)d * SS * G4 * BB;
#pragma unroll
    for (int i = 0; i < 8; i++) {
        int grow = g0 + ty * 8 + i;
        float bias = bih[grow] + bhh[grow];
        float2 p0 = unpk(acc[i][0]);
        float2 p1 = unpk(acc[i][1]);
        float2 p2 = unpk(acc[i][2]);
        float2 p3 = unpk(acc[i][3]);
        size_t off = base_d + (((size_t)t * G4 + grow) << 5) + b0;
        *(float4*)&g_xg[off]     = make_float4(p0.x + bias, p0.y + bias, p1.x + bias, p1.y + bias);
        *(float4*)&g_xg[off + 4] = make_float4(p2.x + bias, p2.y + bias, p3.x + bias, p3.y + bias);
    }
}

// ---------------- persistent recurrence v4: both dirs per block ----------------
// 64 blocks; block owns hidden units 4*blk..4*blk+3 for BOTH directions.
// Each step: fwd phase then bwd phase. The barrier wait for each direction is
// polled by one lane during the OTHER direction's compute and propagated by
// that phase's existing __syncthreads — barrier latency hidden.
// Dynamic smem layout: wp[2][4][256] float4 (32K) | ps 16K | hstF 512 | hstB 512
__global__ __launch_bounds__(256) void k_rec(const float* __restrict__ fWhh,
                                             const float* __restrict__ bWhh,
                                             float* __restrict__ out, int rows)
{
    extern __shared__ __align__(16) char dsm[];
    float4 (*wp)[4][256] = (float4(*)[4][256])dsm;              // [d][rg][k]
    unsigned long long* ps = (unsigned long long*)(dsm + 32768);
    float* hstF = (float*)(dsm + 49152);
    float* hstB = (float*)(dsm + 49664);

    const int blk  = blockIdx.x;      // 0..63
    const int tid  = threadIdx.x;
    const int s    = tid >> 5;        // warp id = k chunk
    const int lane = tid & 31;        // batch

#pragma unroll
    for (int dd = 0; dd < 2; dd++) {
        const float* W = dd ? bWhh : fWhh;
        for (int idx = tid; idx < 1024; idx += 256) {
            int rg = idx >> 8, k = idx & 255;
            int gb4 = blk * 4 + rg;
            wp[dd][rg][k] = make_float4(W[(size_t)(0 * HH + gb4) * HH + k],
                                        W[(size_t)(1 * HH + gb4) * HH + k],
                                        W[(size_t)(2 * HH + gb4) * HH + k],
                                        W[(size_t)(3 * HH + gb4) * HH + k]);
        }
    }

    const float* __restrict__ xgF = g_xg;
    const float* __restrict__ xgB = g_xg + (size_t)SS * G4 * BB;
    const int*   __restrict__ jF  = g_j;
    const int*   __restrict__ jB  = g_j + SS * BB;

    const int u  = s & 3;             // reducer unit (tid<128)
    const int ck = blk * 4 + u;
    float cf = 0.0f, cb = 0.0f;       // cell states fwd / bwd

    const size_t xo0 = ((size_t)(0 * HH + ck) << 5) + lane;
    const size_t xo1 = ((size_t)(1 * HH + ck) << 5) + lane;
    const size_t xo2 = ((size_t)(2 * HH + ck) << 5) + lane;
    const size_t xo3 = ((size_t)(3 * HH + ck) << 5) + lane;
    const int kbase = s * 32;
    __syncthreads();   // wp ready

    for (int t = 0; t < SS; t++) {
        const size_t xb = (size_t)t * (G4 * BB);

        // ================= forward phase =================
        {
            const float* rb = g_hprev[0][t & 1];
            float*       wb = g_hprev[0][(t + 1) & 1];
            float xi = 0, xf = 0, xg_ = 0, xo = 0;
            if (tid < 128) {                       // issue early, consumed post-S1
                xi  = xgF[xb + xo0]; xf = xgF[xb + xo1];
                xg_ = xgF[xb + xo2]; xo = xgF[xb + xo3];
            }
            float hv[32];
#pragma unroll
            for (int kk = 0; kk < 32; kk++)
                hv[kk] = __ldcg(rb + ((kbase + kk) << 5) + lane);

            unsigned long long a0 = 0, a1 = 0, a2 = 0, a3 = 0,
                               a4 = 0, a5 = 0, a6 = 0, a7 = 0;
#pragma unroll
            for (int kk = 0; kk < 32; kk++) {
                int k = kbase + kk;
                unsigned long long hd = dup2(hv[kk]);
                ulonglong2 w01 = *(const ulonglong2*)&wp[0][0][k];
                ulonglong2 w23 = *(const ulonglong2*)&wp[0][1][k];
                ulonglong2 w45 = *(const ulonglong2*)&wp[0][2][k];
                ulonglong2 w67 = *(const ulonglong2*)&wp[0][3][k];
                fma2(a0, w01.x, hd); fma2(a1, w01.y, hd);
                fma2(a2, w23.x, hd); fma2(a3, w23.y, hd);
                fma2(a4, w45.x, hd); fma2(a5, w45.y, hd);
                fma2(a6, w67.x, hd); fma2(a7, w67.y, hd);
            }
            {
                unsigned long long* p = &ps[(s * 8) * 32 + lane];
                p[0 * 32] = a0; p[1 * 32] = a1; p[2 * 32] = a2; p[3 * 32] = a3;
                p[4 * 32] = a4; p[5 * 32] = a5; p[6 * 32] = a6; p[7 * 32] = a7;
            }
            __syncthreads();                               // S1: psum ready
            if (tid < 128) {
                unsigned long long sif = 0, sgo = 0;
#pragma unroll
                for (int s2 = 0; s2 < 8; s2++) {
                    sif = add2(sif, ps[(s2 * 8 + 2 * u) * 32 + lane]);
                    sgo = add2(sgo, ps[(s2 * 8 + 2 * u + 1) * 32 + lane]);
                }
                float2 pif = unpk(sif), pgo = unpk(sgo);
                float gi = pif.x + xi, gf = pif.y + xf;
                float gg = pgo.x + xg_, go = pgo.y + xo;
                cf = sigm(gf) * cf + sigm(gi) * tanhf(gg);
                float h = sigm(go) * tanhf(cf);
                wb[(ck << 5) + lane] = h;
                hstF[lane * 4 + u] = h;
            } else if (tid == 255 && t > 0) {
                // poll bwd barrier for this step (released during others' bwd t-1)
                unsigned tgt = 64u * (unsigned)t, v;
                do {
                    asm volatile("ld.acquire.gpu.u32 %0, [%1];"
                                 : "=r"(v) : "l"(&g_cnt[1]) : "memory");
                } while (v < tgt);
            }
            __syncthreads();                               // S2: h stores + poll done
            if (tid == 224) {
                asm volatile("red.release.gpu.add.u32 [%0], %1;"
                             :: "l"(&g_cnt[0]), "r"(1u) : "memory");
            } else if (tid < 32) {
                int jo = jF[t * BB + tid];
                if (jo >= 0 && jo < rows)
                    *(float4*)(out + ((size_t)tid * rows + jo) * 512 + blk * 4)
                        = *(float4*)&hstF[tid * 4];
            }
        }

        // ================= backward phase =================
        {
            const float* rb = g_hprev[1][t & 1];
            float*       wb = g_hprev[1][(t + 1) & 1];
            float xi = 0, xf = 0, xg_ = 0, xo = 0;
            if (tid < 128) {
                xi  = xgB[xb + xo0]; xf = xgB[xb + xo1];
                xg_ = xgB[xb + xo2]; xo = xgB[xb + xo3];
            }
            float hv[32];
#pragma unroll
            for (int kk = 0; kk < 32; kk++)
                hv[kk] = __ldcg(rb + ((kbase + kk) << 5) + lane);

            unsigned long long a0 = 0, a1 = 0, a2 = 0, a3 = 0,
                               a4 = 0, a5 = 0, a6 = 0, a7 = 0;
#pragma unroll
            for (int kk = 0; kk < 32; kk++) {
                int k = kbase + kk;
                unsigned long long hd = dup2(hv[kk]);
                ulonglong2 w01 = *(const ulonglong2*)&wp[1][0][k];
                ulonglong2 w23 = *(const ulonglong2*)&wp[1][1][k];
                ulonglong2 w45 = *(const ulonglong2*)&wp[1][2][k];
                ulonglong2 w67 = *(const ulonglong2*)&wp[1][3][k];
                fma2(a0, w01.x, hd); fma2(a1, w01.y, hd);
                fma2(a2, w23.x, hd); fma2(a3, w23.y, hd);
                fma2(a4, w45.x, hd); fma2(a5, w45.y, hd);
                fma2(a6, w67.x, hd); fma2(a7, w67.y, hd);
            }
            {
                unsigned long long* p = &ps[(s * 8) * 32 + lane];
                p[0 * 32] = a0; p[1 * 32] = a1; p[2 * 32] = a2; p[3 * 32] = a3;
                p[4 * 32] = a4; p[5 * 32] = a5; p[6 * 32] = a6; p[7 * 32] = a7;
            }
            __syncthreads();                               // S3: psum ready
            if (tid < 128) {
                unsigned long long sif = 0, sgo = 0;
#pragma unroll
                for (int s2 = 0; s2 < 8; s2++) {
                    sif = add2(sif, ps[(s2 * 8 + 2 * u) * 32 + lane]);
                    sgo = add2(sgo, ps[(s2 * 8 + 2 * u + 1) * 32 + lane]);
                }
                float2 pif = unpk(sif), pgo = unpk(sgo);
                float gi = pif.x + xi, gf = pif.y + xf;
                float gg = pgo.x + xg_, go = pgo.y + xo;
                cb = sigm(gf) * cb + sigm(gi) * tanhf(gg);
                float h = sigm(go) * tanhf(cb);
                wb[(ck << 5) + lane] = h;
                hstB[lane * 4 + u] = h;
            } else if (tid == 255 && t + 1 < SS) {
                // poll fwd barrier for next step (released during others' fwd t)
                unsigned tgt = 64u * (unsigned)(t + 1), v;
                do {
                    asm volatile("ld.acquire.gpu.u32 %0, [%1];"
                                 : "=r"(v) : "l"(&g_cnt[0]) : "memory");
                } while (v < tgt);
            }
            __syncthreads();                               // S4: h stores + poll done
            if (tid == 224) {
                asm volatile("red.release.gpu.add.u32 [%0], %1;"
                             :: "l"(&g_cnt[1]), "r"(1u) : "memory");
            } else if (tid < 32) {
                int jo = jB[t * BB + tid];
                if (jo >= 0 && jo < rows)
                    *(float4*)(out + ((size_t)tid * rows + jo) * 512 + 256 + blk * 4)
                        = *(float4*)&hstB[tid * 4];
            }
        }
    }
}

// ---------------- launch ------------------------------------------------------
extern "C" void kernel_launch(void* const* d_in, const int* in_sizes, int n_in,
                              void* d_out, int out_size)
{
    const int*   inputs = (const int*)d_in[0];
    const int*   seqlen = (const int*)d_in[1];
    const int*   fmask  = (const int*)d_in[2];
    // d_in[3] = bmask (unused by the reference math)
    int base = (in_sizes[4] == 1) ? 5 : 4;   // skip out_seq_length scalar if present
    const float* emb   = (const float*)d_in[base + 0];
    const float* f_Wih = (const float*)d_in[base + 1];
    const float* f_Whh = (const float*)d_in[base + 2];
    const float* f_bih = (const float*)d_in[base + 3];
    const float* f_bhh = (const float*)d_in[base + 4];
    const float* b_Wih = (const float*)d_in[base + 5];
    const float* b_Whh = (const float*)d_in[base + 6];
    const float* b_bih = (const float*)d_in[base + 7];
    const float* b_bhh = (const float*)d_in[base + 8];
    (void)n_in;

    int rows = out_size / (BB * 512);        // out_seq_length

    static int smem_set = 0;
    if (!smem_set) {
        cudaFuncSetAttribute(k_rec, cudaFuncAttributeMaxDynamicSharedMemorySize, 50176);
        smem_set = 1;
    }

    cudaMemsetAsync(d_out, 0, (size_t)out_size * sizeof(float), 0);
    k_prep<<<BB, SS>>>(inputs, seqlen, fmask);
    k_wt<<<dim3(32, 16, 2), 256>>>(f_Wih, b_Wih);
    k_gemm<<<dim3(256, 8, 2), 256>>>(emb, f_bih, f_bhh, b_bih, b_bhh);
    k_rec<<<64, 256, 50176>>>(f_Whh, b_Whh, (float*)d_out, rows);
}

// round 14
// speedup vs baseline: 1.5613x; 1.5613x over previous
#include <cuda_runtime.h>
#include <cuda_bf16.h>
#include <math.h>
#include <stdint.h>

#define BB 32
#define SS 1024
#define EE 512
#define HH 256
#define G4 1024
#define VV 50000

__device__ float    g_xg[(size_t)2 * SS * G4 * BB];
__device__ int      g_tok[2 * SS * BB];
__device__ int      g_j[2 * SS * BB];
__device__ float    g_hprev[2][2][HH * BB];
__device__ unsigned g_cnt[2];
__device__ __nv_bfloat16 g_Eh[(size_t)VV * EE];
__device__ __nv_bfloat16 g_El[(size_t)VV * EE];
__device__ __nv_bfloat16 g_Wh[2][(size_t)G4 * EE];
__device__ __nv_bfloat16 g_Wl[2][(size_t)G4 * EE];

__device__ __forceinline__ float sigm(float x) { return 1.0f / (1.0f + __expf(-x)); }
__device__ __forceinline__ void fma2(unsigned long long &d,
                                     unsigned long long a, unsigned long long b) {
    asm("fma.rn.f32x2 %0, %1, %2, %0;" : "+l"(d) : "l"(a), "l"(b));
}
__device__ __forceinline__ unsigned long long add2(unsigned long long a,
                                                   unsigned long long b) {
    unsigned long long r;
    asm("add.rn.f32x2 %0, %1, %2;" : "=l"(r) : "l"(a), "l"(b));
    return r;
}
__device__ __forceinline__ unsigned long long dup2(float x) {
    unsigned long long r; asm("mov.b64 %0, {%1, %1};" : "=l"(r) : "f"(x)); return r;
}
__device__ __forceinline__ float2 unpk(unsigned long long v) {
    float2 r; asm("mov.b64 {%0, %1}, %2;" : "=f"(r.x), "=f"(r.y) : "l"(v)); return r;
}
__device__ __forceinline__ uint32_t s2u(const void* p) {
    uint32_t a;
    asm("{ .reg .u64 t; cvta.to.shared.u64 t, %1; cvt.u32.u64 %0, t; }" : "=r"(a) : "l"(p));
    return a;
}

#define LDSM4(r, a) \
    asm volatile("ldmatrix.sync.aligned.m8n8.x4.shared.b16 {%0,%1,%2,%3}, [%4];" \
                 : "=r"((r)[0]), "=r"((r)[1]), "=r"((r)[2]), "=r"((r)[3]) : "r"(a))
#define MMA(d, a, b0, b1) \
    asm volatile("mma.sync.aligned.m16n8k16.row.col.f32.bf16.bf16.f32 " \
        "{%0,%1,%2,%3}, {%4,%5,%6,%7}, {%8,%9}, {%0,%1,%2,%3};" \
        : "+f"((d)[0]), "+f"((d)[1]), "+f"((d)[2]), "+f"((d)[3]) \
        : "r"((a)[0]), "r"((a)[1]), "r"((a)[2]), "r"((a)[3]), "r"(b0), "r"(b1))

// ---- prep ----
__global__ __launch_bounds__(1024) void k_prep(const int* __restrict__ inputs,
                                               const int* __restrict__ seqlen,
                                               const int* __restrict__ fmask)
{
    int b = blockIdx.x, t = threadIdx.x;
    __shared__ int sc[SS];
    int m = (fmask[b * SS + t] != 0) ? 1 : 0;
    sc[t] = m;
    __syncthreads();
    for (int off = 1; off < SS; off <<= 1) {
        int v = (t >= off) ? sc[t - off] : 0;
        __syncthreads();
        sc[t] += v;
        __syncthreads();
    }
    int r = sc[t], cnt = sc[SS - 1];
    g_j[t * BB + b]           = m ? (r - 1)   : -1;
    g_j[SS * BB + t * BB + b] = m ? (cnt - r) : -1;
    int len = seqlen[b];
    g_tok[t * BB + b] = inputs[b * SS + t];
    g_tok[SS * BB + t * BB + b] = (t < len) ? inputs[b * SS + (len - 1 - t)] : 0;
    if (b == 0) {
        for (int i = t; i < 2 * HH * BB; i += 1024) {
            int d = i / (HH * BB);
            g_hprev[d][0][i - d * HH * BB] = 0.0f;
        }
        if (t < 2) g_cnt[t] = 0u;
    }
}

// ---- bf16 hi/lo preconversion ----
__global__ __launch_bounds__(256) void k_cvt_e(const float* __restrict__ emb) {
    size_t i = (size_t)blockIdx.x * 256 + threadIdx.x;
    float x = emb[i];
    __nv_bfloat16 h = __float2bfloat16(x);
    g_Eh[i] = h;
    g_El[i] = __float2bfloat16(x - __bfloat162float(h));
}
__global__ __launch_bounds__(256) void k_cvt_w(const float* __restrict__ fW,
                                               const float* __restrict__ bW) {
    size_t i = (size_t)blockIdx.x * 256 + threadIdx.x;
    int d = (i >= (size_t)G4 * EE);
    size_t j = i - (size_t)d * G4 * EE;
    float x = d ? bW[j] : fW[j];
    __nv_bfloat16 h = __float2bfloat16(x);
    g_Wh[d][j] = h;
    g_Wl[d][j] = __float2bfloat16(x - __bfloat162float(h));
}

// ---- mma.sync GEMM: block = 128 tokens x 128 gates, K=512 in 16 chunks ----
// smem: A hi 0..10240, A lo 10240.., B hi 20480.., B lo 30720.., ts 40960, bias 41472
__global__ __launch_bounds__(256) void k_mgemm(
    const float* __restrict__ fbih, const float* __restrict__ fbhh,
    const float* __restrict__ bbih, const float* __restrict__ bbhh)
{
    __shared__ __align__(16) char smc[41984];
    const uint32_t smb = s2u(smc);
    const int d  = blockIdx.z;
    const int mt = blockIdx.y;
    const int gt = blockIdx.x;
    const int tid = threadIdx.x, wid = tid >> 5, lane = tid & 31;
    const int warp_m = wid & 3, warp_n = wid >> 2;

    int*   ts   = (int*)(smc + 40960);
    float* bias = (float*)(smc + 41472);
    if (tid < 128) ts[tid] = g_tok[d * SS * BB + mt * 128 + tid];
    {
        const float* bi = d ? bbih : fbih;
        const float* bh = d ? bbhh : fbhh;
        if (tid < 128) bias[tid] = bi[gt * 128 + tid] + bh[gt * 128 + tid];
    }
    __syncthreads();

    const __nv_bfloat16* __restrict__ Wh = g_Wh[d];
    const __nv_bfloat16* __restrict__ Wl = g_Wl[d];

    // per-thread load slots
    const int rA0 = tid >> 2, rA1 = rA0 + 64;
    const int kq  = tid & 3;
    const int tb0 = ts[rA0] * EE + kq * 8;
    const int tb1 = ts[rA1] * EE + kq * 8;
    const int wb0 = (gt * 128 + rA0) * EE + kq * 8;
    const int wb1 = (gt * 128 + rA1) * EE + kq * 8;
    const int dA0 = rA0 * 80 + kq * 16;
    const int dA1 = rA1 * 80 + kq * 16;

    // ldmatrix base addresses
    const uint32_t aBase = smb + (uint32_t)((warp_m * 32 + (lane & 15)) * 80
                                            + ((lane >> 4) & 1) * 16);
    const uint32_t bBase = smb + 20480u
        + (uint32_t)((warp_n * 64 + ((lane >> 3) & 1) * 8 + (lane & 7)) * 80
                     + ((lane >> 4) & 1) * 16);

    float acc[2][8][4];
#pragma unroll
    for (int m = 0; m < 2; m++)
#pragma unroll
        for (int n = 0; n < 8; n++)
#pragma unroll
            for (int q = 0; q < 4; q++) acc[m][n][q] = 0.0f;

    uint4 pa0h = *(const uint4*)(g_Eh + tb0);
    uint4 pa1h = *(const uint4*)(g_Eh + tb1);
    uint4 pa0l = *(const uint4*)(g_El + tb0);
    uint4 pa1l = *(const uint4*)(g_El + tb1);
    uint4 pb0h = *(const uint4*)(Wh + wb0);
    uint4 pb1h = *(const uint4*)(Wh + wb1);
    uint4 pb0l = *(const uint4*)(Wl + wb0);
    uint4 pb1l = *(const uint4*)(Wl + wb1);

    for (int ch = 0; ch < 16; ch++) {
        *(uint4*)(smc + dA0)         = pa0h;
        *(uint4*)(smc + dA1)         = pa1h;
        *(uint4*)(smc + 10240 + dA0) = pa0l;
        *(uint4*)(smc + 10240 + dA1) = pa1l;
        *(uint4*)(smc + 20480 + dA0) = pb0h;
        *(uint4*)(smc + 20480 + dA1) = pb1h;
        *(uint4*)(smc + 30720 + dA0) = pb0l;
        *(uint4*)(smc + 30720 + dA1) = pb1l;
        __syncthreads();

        if (ch < 15) {
            int k0 = (ch + 1) * 32;
            pa0h = *(const uint4*)(g_Eh + tb0 + k0);
            pa1h = *(const uint4*)(g_Eh + tb1 + k0);
            pa0l = *(const uint4*)(g_El + tb0 + k0);
            pa1l = *(const uint4*)(g_El + tb1 + k0);
            pb0h = *(const uint4*)(Wh + wb0 + k0);
            pb1h = *(const uint4*)(Wh + wb1 + k0);
            pb0l = *(const uint4*)(Wl + wb0 + k0);
            pb1l = *(const uint4*)(Wl + wb1 + k0);
        }

#pragma unroll
        for (int ks = 0; ks < 2; ks++) {
            uint32_t ko = ks * 32;
            uint32_t Ah0[4], Ah1[4], Al0[4], Al1[4];
            LDSM4(Ah0, aBase + ko);
            LDSM4(Ah1, aBase + 1280 + ko);
            LDSM4(Al0, aBase + 10240 + ko);
            LDSM4(Al1, aBase + 11520 + ko);
#pragma unroll
            for (int p = 0; p < 4; p++) {
                uint32_t Bh[4], Bl[4];
                LDSM4(Bh, bBase + p * 1280 + ko);
                LDSM4(Bl, bBase + 10240 + p * 1280 + ko);
                MMA(acc[0][2 * p],     Ah0, Bh[0], Bh[2]);
                MMA(acc[0][2 * p + 1], Ah0, Bh[1], Bh[3]);
                MMA(acc[1][2 * p],     Ah1, Bh[0], Bh[2]);
                MMA(acc[1][2 * p + 1], Ah1, Bh[1], Bh[3]);
                MMA(acc[0][2 * p],     Al0, Bh[0], Bh[2]);
                MMA(acc[0][2 * p + 1], Al0, Bh[1], Bh[3]);
                MMA(acc[1][2 * p],     Al1, Bh[0], Bh[2]);
                MMA(acc[1][2 * p + 1], Al1, Bh[1], Bh[3]);
                MMA(acc[0][2 * p],     Ah0, Bl[0], Bl[2]);
                MMA(acc[0][2 * p + 1], Ah0, Bl[1], Bl[3]);
                MMA(acc[1][2 * p],     Ah1, Bl[0], Bl[2]);
                MMA(acc[1][2 * p + 1], Ah1, Bl[1], Bl[3]);
            }
        }
        __syncthreads();
    }

    // epilogue: stage halves (64 tok x 128 g) in smem -> coalesced xg stores
    float* st = (float*)smc;
    float* __restrict__ xgd = g_xg + (size_t)d * SS * G4 * BB;
    const int gid = lane >> 2, tig = lane & 3;
#pragma unroll
    for (int half = 0; half < 2; half++) {
        __syncthreads();
        if ((warp_m >> 1) == half) {
            int rbase = (warp_m & 1) * 32;
#pragma unroll
            for (int m = 0; m < 2; m++) {
                int row0 = rbase + m * 16 + gid;
#pragma unroll
                for (int nt = 0; nt < 8; nt++) {
                    int col = warp_n * 64 + nt * 8 + tig * 2;
                    st[row0 * 130 + col]           = acc[m][nt][0];
                    st[row0 * 130 + col + 1]       = acc[m][nt][1];
                    st[(row0 + 8) * 130 + col]     = acc[m][nt][2];
                    st[(row0 + 8) * 130 + col + 1] = acc[m][nt][3];
                }
            }
        }
        __syncthreads();
#pragma unroll
        for (int i = 0; i < 32; i++) {
            int c = i * 8 + wid;
            int tl = c >> 7, g = c & 127;
            float v = st[(tl * 32 + lane) * 130 + g] + bias[g];
            int t = mt * 4 + half * 2 + tl;
            xgd[(((size_t)t * G4 + gt * 128 + g) << 5) + lane] = v;
        }
    }
}

// ---- persistent recurrence (R7 verbatim) ----
__global__ __launch_bounds__(256) void k_rec(const float* __restrict__ fWhh,
                                             const float* __restrict__ bWhh,
                                             float* __restrict__ out, int rows)
{
    __shared__ __align__(16) float4 wp4[4][256];
    __shared__ __align__(16) unsigned long long ps[2048];
    __shared__ float hstage[128];

    const int d = blockIdx.x >> 6, blk = blockIdx.x & 63;
    const float* __restrict__ Whh = d ? bWhh : fWhh;
    const int tid = threadIdx.x, s = tid >> 5, lane = tid & 31;

    for (int idx = tid; idx < 1024; idx += 256) {
        int rg = idx >> 8, k = idx & 255;
        int gb4 = blk * 4 + rg;
        wp4[rg][k] = make_float4(Whh[(size_t)(0 * HH + gb4) * HH + k],
                                 Whh[(size_t)(1 * HH + gb4) * HH + k],
                                 Whh[(size_t)(2 * HH + gb4) * HH + k],
                                 Whh[(size_t)(3 * HH + gb4) * HH + k]);
    }
    const float* __restrict__ xgd = g_xg + (size_t)d * SS * G4 * BB;
    const int*   __restrict__ jd_arr = g_j + d * SS * BB;
    unsigned* cnt = &g_cnt[d];
    const int u = s & 3, ck = blk * 4 + u;
    float c = 0.0f;
    size_t xoff0 = ((size_t)(0 * HH + ck) << 5) + lane;
    size_t xoff1 = ((size_t)(1 * HH + ck) << 5) + lane;
    size_t xoff2 = ((size_t)(2 * HH + ck) << 5) + lane;
    size_t xoff3 = ((size_t)(3 * HH + ck) << 5) + lane;
    float xi = 0, xf = 0, xgg = 0, xo = 0;
    if (tid < 128) { xi = xgd[xoff0]; xf = xgd[xoff1]; xgg = xgd[xoff2]; xo = xgd[xoff3]; }
    int jreg = (tid < 32) ? jd_arr[tid] : -1;
    const int kbase = s * 32;
    const size_t outbase = (size_t)d * 256 + blk * 4;
    __syncthreads();

    for (int t = 0; t < SS; t++) {
        const float* rbuf = g_hprev[d][t & 1];
        float*       wbuf = g_hprev[d][(t + 1) & 1];
        float hv[32];
#pragma unroll
        for (int kk = 0; kk < 32; kk++)
            hv[kk] = __ldcg(rbuf + ((kbase + kk) << 5) + lane);
        unsigned long long a0 = 0, a1 = 0, a2 = 0, a3 = 0, a4 = 0, a5 = 0, a6 = 0, a7 = 0;
#pragma unroll
        for (int kk = 0; kk < 32; kk++) {
            int k = kbase + kk;
            unsigned long long hd = dup2(hv[kk]);
            ulonglong2 w01 = *(const ulonglong2*)&wp4[0][k];
            ulonglong2 w23 = *(const ulonglong2*)&wp4[1][k];
            ulonglong2 w45 = *(const ulonglong2*)&wp4[2][k];
            ulonglong2 w67 = *(const ulonglong2*)&wp4[3][k];
            fma2(a0, w01.x, hd); fma2(a1, w01.y, hd);
            fma2(a2, w23.x, hd); fma2(a3, w23.y, hd);
            fma2(a4, w45.x, hd); fma2(a5, w45.y, hd);
            fma2(a6, w67.x, hd); fma2(a7, w67.y, hd);
        }
        {
            unsigned long long* p = &ps[(s * 8) * 32 + lane];
            p[0] = a0; p[32] = a1; p[64] = a2; p[96] = a3;
            p[128] = a4; p[160] = a5; p[192] = a6; p[224] = a7;
        }
        __syncthreads();
        if (tid < 128) {
            unsigned long long sif = 0, sgo = 0;
#pragma unroll
            for (int s2 = 0; s2 < 8; s2++) {
                sif = add2(sif, ps[(s2 * 8 + 2 * u) * 32 + lane]);
                sgo = add2(sgo, ps[(s2 * 8 + 2 * u + 1) * 32 + lane]);
            }
            float2 pif = unpk(sif), pgo = unpk(sgo);
            float gi = pif.x + xi, gf = pif.y + xf;
            float gg = pgo.x + xgg, go = pgo.y + xo;
            c = sigm(gf) * c + sigm(gi) * tanhf(gg);
            float h = sigm(go) * tanhf(c);
            wbuf[(ck << 5) + lane] = h;
            hstage[lane * 4 + u] = h;
            int tn = (t + 1 < SS) ? (t + 1) : t;
            size_t xb = (size_t)tn * (G4 * BB);
            xi = xgd[xb + xoff0]; xf = xgd[xb + xoff1];
            xgg = xgd[xb + xoff2]; xo = xgd[xb + xoff3];
        }
        __syncthreads();
        if (tid < 32) {
            int jo = jreg;
            if (jo >= 0 && jo < rows) {
                float4 hvv = *(float4*)&hstage[tid * 4];
                *(float4*)(out + ((size_t)tid * rows + jo) * 512 + outbase) = hvv;
            }
            int tn = (t + 1 < SS) ? (t + 1) : t;
            jreg = jd_arr[tn * BB + tid];
        } else if (tid == 224) {
            asm volatile("red.release.gpu.add.u32 [%0], %1;" :: "l"(cnt), "r"(1u) : "memory");
            unsigned target = 64u * (unsigned)(t + 1), v;
            do {
                asm volatile("ld.acquire.gpu.u32 %0, [%1];" : "=r"(v) : "l"(cnt) : "memory");
            } while (v < target);
        }
        __syncthreads();
    }
}

// ---- launch ----
extern "C" void kernel_launch(void* const* d_in, const int* in_sizes, int n_in,
                              void* d_out, int out_size)
{
    const int* inputs = (const int*)d_in[0];
    const int* seqlen = (const int*)d_in[1];
    const int* fmask  = (const int*)d_in[2];
    int base = (in_sizes[4] == 1) ? 5 : 4;
    const float* emb   = (const float*)d_in[base + 0];
    const float* f_Wih = (const float*)d_in[base + 1];
    const float* f_Whh = (const float*)d_in[base + 2];
    const float* f_bih = (const float*)d_in[base + 3];
    const float* f_bhh = (const float*)d_in[base + 4];
    const float* b_Wih = (const float*)d_in[base + 5];
    const float* b_Whh = (const float*)d_in[base + 6];
    const float* b_bih = (const float*)d_in[base + 7];
    const float* b_bhh = (const float*)d_in[base + 8];
    (void)n_in;
    int rows = out_size / (BB * 512);

    cudaMemsetAsync(d_out, 0, (size_t)out_size * sizeof(float), 0);
    k_prep<<<BB, SS>>>(inputs, seqlen, fmask);
    k_cvt_e<<<(VV * EE) / 256, 256>>>(emb);
    k_cvt_w<<<(2 * G4 * EE) / 256, 256>>>(f_Wih, b_Wih);
    k_mgemm<<<dim3(8, 256, 2), 256>>>(f_bih, f_bhh, b_bih, b_bhh);
    k_rec<<<128, 256>>>(f_Whh, b_Whh, (float*)d_out, rows);
}